// round 6
// baseline (speedup 1.0000x reference)
#include <cuda_runtime.h>
#include <math.h>

constexpr int H = 256;
constexpr int B = 4;
constexpr int S = 128;
constexpr int T = 128;

typedef unsigned long long ull;

// Scratch (device globals — no allocation allowed)
__device__ float g_pre_x[(size_t)B * S * T * H];
__device__ float g_pre_y[(size_t)B * S * T * H];
__device__ float g_hx  [(size_t)B * S * T * H];
__device__ float g_hy  [(size_t)B * S * T * H];
__device__ float g_psx [(size_t)B * S * H];
__device__ float g_psy [(size_t)B * T * H];
__device__ unsigned g_flags[128];   // [path(2)][rowtile(16)][coltile(4)]

// ---------------- packed f32x2 helpers ----------------
__device__ __forceinline__ ull pack2(float x) {
    ull r; asm("mov.b64 %0, {%1, %1};" : "=l"(r) : "f"(x)); return r;
}
__device__ __forceinline__ void ffma2(ull& d, ull a, ull b) {
    asm("fma.rn.f32x2 %0, %1, %2, %0;" : "+l"(d) : "l"(a), "l"(b));
}
__device__ __forceinline__ float2 unpack2(ull v) {
    float2 f; asm("mov.b64 {%0, %1}, %2;" : "=f"(f.x), "=f"(f.y) : "l"(v)); return f;
}
__device__ __forceinline__ unsigned ld_acq(const unsigned* p) {
    unsigned v;
    asm volatile("ld.global.acquire.gpu.u32 %0, [%1];" : "=r"(v) : "l"(p) : "memory");
    return v;
}
__device__ __forceinline__ void st_rel(unsigned* p, unsigned v) {
    asm volatile("st.global.release.gpu.u32 [%0], %1;" :: "l"(p), "r"(v) : "memory");
}

// Accurate tanh regardless of --use_fast_math
__device__ __forceinline__ float my_tanh(float x) {
    float ax = fabsf(x);
    float e  = expf(-2.0f * ax);
    float t  = (1.0f - e) / (1.0f + e);
    return x < 0.0f ? -t : t;
}

__global__ void reset_flags_kernel() { g_flags[threadIdx.x] = 0; }

// ---------------------------------------------------------------------------
// Prepass GEMM (f32x2): C[m,n] = sum_k A[m,k]*W[n,k] + b1[n] + b2[n]
// N=K=256. BM=BN=64, BK=32, 256 thr, 4 rows x 4 cols per thread.
// A staged duplicated ({v,v}) so FFMA2 broadcast operand is one LDS.64.
// ---------------------------------------------------------------------------
__global__ void __launch_bounds__(256) gemm256_bias(
    const float* __restrict__ A, const float* __restrict__ W,
    const float* __restrict__ b1, const float* __restrict__ b2,
    float* __restrict__ C)
{
    __shared__ float As[32 * 132];   // [k][2*m], duplicated pairs
    __shared__ float Bs[32 * 68];    // [k][n]

    const int m0  = blockIdx.x << 6;
    const int n0  = blockIdx.y << 6;
    const int tid = threadIdx.x;
    const int tx  = tid & 15;        // n sub-tile (4 cols)
    const int ty  = tid >> 4;        // m sub-tile (4 rows)
    const int lr  = tid >> 2;        // 0..63 load row
    const int lk  = (tid & 3) << 2;  // 0,4,8,12

    const float* Ap = A + (size_t)(m0 + lr) * H + lk;
    const float* Wp = W + (size_t)(n0 + lr) * H + lk;

    float4 ra0 = *(const float4*)(Ap);
    float4 ra1 = *(const float4*)(Ap + 16);
    float4 rw0 = *(const float4*)(Wp);
    float4 rw1 = *(const float4*)(Wp + 16);

    ull acc[4][2] = {};

    for (int c = 0; c < 8; c++) {
        *(float2*)&As[(lk + 0) * 132 + (lr << 1)] = make_float2(ra0.x, ra0.x);
        *(float2*)&As[(lk + 1) * 132 + (lr << 1)] = make_float2(ra0.y, ra0.y);
        *(float2*)&As[(lk + 2) * 132 + (lr << 1)] = make_float2(ra0.z, ra0.z);
        *(float2*)&As[(lk + 3) * 132 + (lr << 1)] = make_float2(ra0.w, ra0.w);
        *(float2*)&As[(lk + 16) * 132 + (lr << 1)] = make_float2(ra1.x, ra1.x);
        *(float2*)&As[(lk + 17) * 132 + (lr << 1)] = make_float2(ra1.y, ra1.y);
        *(float2*)&As[(lk + 18) * 132 + (lr << 1)] = make_float2(ra1.z, ra1.z);
        *(float2*)&As[(lk + 19) * 132 + (lr << 1)] = make_float2(ra1.w, ra1.w);
        Bs[(lk + 0) * 68 + lr] = rw0.x;  Bs[(lk + 1) * 68 + lr] = rw0.y;
        Bs[(lk + 2) * 68 + lr] = rw0.z;  Bs[(lk + 3) * 68 + lr] = rw0.w;
        Bs[(lk + 16) * 68 + lr] = rw1.x; Bs[(lk + 17) * 68 + lr] = rw1.y;
        Bs[(lk + 18) * 68 + lr] = rw1.z; Bs[(lk + 19) * 68 + lr] = rw1.w;
        __syncthreads();

        if (c < 7) {
            int k = (c + 1) << 5;
            ra0 = *(const float4*)(Ap + k);
            ra1 = *(const float4*)(Ap + k + 16);
            rw0 = *(const float4*)(Wp + k);
            rw1 = *(const float4*)(Wp + k + 16);
        }

        const float* aB = As + (ty << 3);   // ty*4 rows, duplicated
        const float* bB = Bs + (tx << 2);
        #pragma unroll
        for (int kk = 0; kk < 32; kk++) {
            ull a0 = *(const ull*)(aB + kk * 132);
            ull a1 = *(const ull*)(aB + kk * 132 + 2);
            ull a2 = *(const ull*)(aB + kk * 132 + 4);
            ull a3 = *(const ull*)(aB + kk * 132 + 6);
            ulonglong2 bb = *(const ulonglong2*)(bB + kk * 68);
            ffma2(acc[0][0], a0, bb.x); ffma2(acc[0][1], a0, bb.y);
            ffma2(acc[1][0], a1, bb.x); ffma2(acc[1][1], a1, bb.y);
            ffma2(acc[2][0], a2, bb.x); ffma2(acc[2][1], a2, bb.y);
            ffma2(acc[3][0], a3, bb.x); ffma2(acc[3][1], a3, bb.y);
        }
        __syncthreads();
    }

    const int n = n0 + (tx << 2);
    float4 bv;
    bv.x = b1[n + 0] + b2[n + 0];
    bv.y = b1[n + 1] + b2[n + 1];
    bv.z = b1[n + 2] + b2[n + 2];
    bv.w = b1[n + 3] + b2[n + 3];

    #pragma unroll
    for (int i = 0; i < 4; i++) {
        float2 p0 = unpack2(acc[i][0]);
        float2 p1 = unpack2(acc[i][1]);
        float4 o;
        o.x = p0.x + bv.x;  o.y = p0.y + bv.y;
        o.z = p1.x + bv.z;  o.w = p1.y + bv.w;
        *(float4*)(C + (size_t)(m0 + (ty << 2) + i) * H + n) = o;
    }
}

// ---------------------------------------------------------------------------
// Persistent recurrence kernel: one launch per depth, 128 steps inside.
// Grid (4 coltiles, 16 rowtiles, 2 paths) = 128 CTAs, 1/SM, all co-resident.
// W_hh tile (64 cols x 256 k) resident in SMEM for the whole depth.
// Cross-step ordering via release/acquire flags in L2 (one per tile).
// ---------------------------------------------------------------------------
struct RArgs {
    const float* W;
    const float* pre; int p_sstep, p_sb, p_sq;
    float*       out; int o_sstep, o_sb, o_sq;
};

constexpr int RECUR_SMEM = (256 * 68 + 256 * 68) * 4;   // Ws + As(dup) = 136 KB

__global__ void __launch_bounds__(256, 1) recur_depth(RArgs AX, RArgs AY, int flag_base)
{
    extern __shared__ float smem_[];
    float* Ws = smem_;               // [k=256][n=64 + pad] stride 68
    float* As = smem_ + 256 * 68;    // [k=256][2*32 rows + pad] stride 68, duplicated

    const int path = blockIdx.z;
    const RArgs P = path ? AY : AX;
    const int bx  = blockIdx.x;      // col tile 0..3
    const int by  = blockIdx.y;      // row tile 0..15
    const int tid = threadIdx.x;
    // lane remap: warp covers 8 tx x 4 ty -> smem crossbar 192B/warp/k
    const int tx  = (tid & 7) | ((tid >> 4) & 8);          // 0..15 (4 cols each)
    const int ty  = ((tid >> 3) & 3) | (((tid >> 5) & 3) << 2); // 0..15 (2 rows each)
    const int n0  = bx << 6;
    const int b   = by >> 2;           // batch
    const int q0  = (by & 3) << 5;     // row offset within batch

    // ---- load W tile into SMEM (once per depth) ----
    {
        const int wr = tid >> 2, wlk = (tid & 3) << 2;
        const float* Wp = P.W + (size_t)(n0 + wr) * H + wlk;
        #pragma unroll
        for (int c = 0; c < 8; c++) {
            float4 w0 = *(const float4*)(Wp + (c << 5));
            float4 w1 = *(const float4*)(Wp + (c << 5) + 16);
            const int k = (c << 5) + wlk;
            Ws[(k + 0) * 68 + wr] = w0.x;  Ws[(k + 1) * 68 + wr] = w0.y;
            Ws[(k + 2) * 68 + wr] = w0.z;  Ws[(k + 3) * 68 + wr] = w0.w;
            Ws[(k + 16) * 68 + wr] = w1.x; Ws[(k + 17) * 68 + wr] = w1.y;
            Ws[(k + 18) * 68 + wr] = w1.z; Ws[(k + 19) * 68 + wr] = w1.w;
        }
    }

    // ---- flag wiring ----
    unsigned* myFlag = &g_flags[(path * 16 + by) * 4 + bx];
    const unsigned* pollPtr = nullptr;
    if (path == 0) {
        // x-path: own row tile (4 col flags) + wrapped-neighbor row tile (4)
        if (tid < 8) {
            int byp = (tid < 4) ? by : ((by & 12) | (((by & 3) + 3) & 3));
            pollPtr = &g_flags[byp * 4 + (tid & 3)];
        }
    } else {
        if (tid < 4) pollPtr = &g_flags[(16 + by) * 4 + tid];
    }

    const int ar  = tid >> 3;          // 0..31 state row
    const int alk = (tid & 7) << 2;    // 0..28
    const int qs  = (path == 0) ? ((q0 + ar + 127) & 127) : (q0 + ar);
    const int qr  = q0 + (ty << 1);

    __syncthreads();

    for (int st = 0; st < 128; st++) {
        // prefetch pre (independent of flags; hides DRAM latency under poll+GEMM)
        const float* pp = P.pre + (size_t)st * P.p_sstep + (size_t)b * P.p_sb
                                + n0 + (tx << 2);
        const float4 pv0 = *(const float4*)(pp + (size_t)qr * P.p_sq);
        const float4 pv1 = *(const float4*)(pp + (size_t)(qr + 1) * P.p_sq);

        ull acc00 = 0, acc01 = 0, acc10 = 0, acc11 = 0;

        if (st > 0) {
            if (pollPtr) {
                const unsigned tgt = (unsigned)(flag_base + st);
                while (ld_acq(pollPtr) < tgt) { }
            }
            __syncthreads();

            // stage state rows (duplicated {v,v}) into As
            const float* sp = P.out + (size_t)(st - 1) * P.o_sstep
                                    + (size_t)b * P.o_sb + (size_t)qs * P.o_sq + alk;
            #pragma unroll
            for (int c = 0; c < 8; c++) {
                float4 v = *(const float4*)(sp + (c << 5));
                const int k = (c << 5) + alk;
                *(float2*)&As[(k + 0) * 68 + (ar << 1)] = make_float2(v.x, v.x);
                *(float2*)&As[(k + 1) * 68 + (ar << 1)] = make_float2(v.y, v.y);
                *(float2*)&As[(k + 2) * 68 + (ar << 1)] = make_float2(v.z, v.z);
                *(float2*)&As[(k + 3) * 68 + (ar << 1)] = make_float2(v.w, v.w);
            }
            __syncthreads();

            // 32x64x256 tile GEMM, FFMA2 inner loop
            const float* aB = As + (ty << 2);
            const float* bB = Ws + (tx << 2);
            #pragma unroll 16
            for (int kk = 0; kk < 256; kk++) {
                ull a0 = *(const ull*)(aB + kk * 68);
                ull a1 = *(const ull*)(aB + kk * 68 + 2);
                ulonglong2 bb = *(const ulonglong2*)(bB + kk * 68);
                ffma2(acc00, a0, bb.x); ffma2(acc01, a0, bb.y);
                ffma2(acc10, a1, bb.x); ffma2(acc11, a1, bb.y);
            }
        }

        // epilogue: tanh(acc + pre) -> out
        float2 r00 = unpack2(acc00), r01 = unpack2(acc01);
        float2 r10 = unpack2(acc10), r11 = unpack2(acc11);
        float4 o0, o1;
        o0.x = my_tanh(r00.x + pv0.x); o0.y = my_tanh(r00.y + pv0.y);
        o0.z = my_tanh(r01.x + pv0.z); o0.w = my_tanh(r01.y + pv0.w);
        o1.x = my_tanh(r10.x + pv1.x); o1.y = my_tanh(r10.y + pv1.y);
        o1.z = my_tanh(r11.x + pv1.z); o1.w = my_tanh(r11.y + pv1.w);

        float* op = P.out + (size_t)st * P.o_sstep + (size_t)b * P.o_sb + n0 + (tx << 2);
        *(float4*)(op + (size_t)qr * P.o_sq)       = o0;
        *(float4*)(op + (size_t)(qr + 1) * P.o_sq) = o1;

        __threadfence();
        __syncthreads();
        if (tid == 0) st_rel(myFlag, (unsigned)(flag_base + st + 1));
    }
}

// ---------------------------------------------------------------------------
// Host orchestration: 10 launches total (flag reset + 3x(prepass + recur)).
// ---------------------------------------------------------------------------
extern "C" void kernel_launch(void* const* d_in, const int* in_sizes, int n_in,
                              void* d_out, int out_size)
{
    const float* src   = (const float*)d_in[0];
    const float* trg   = (const float*)d_in[1];
    const float* Wx_ih = (const float*)d_in[2];
    const float* Wx_hh = (const float*)d_in[3];
    const float* bx_ih = (const float*)d_in[4];
    const float* bx_hh = (const float*)d_in[5];
    const float* Wy_ih = (const float*)d_in[6];
    const float* Wy_hh = (const float*)d_in[7];
    const float* by_ih = (const float*)d_in[8];
    const float* by_hh = (const float*)d_in[9];
    float* out = (float*)d_out;

    float *pre_x, *pre_y, *hx, *hy, *psx, *psy;
    cudaGetSymbolAddress((void**)&pre_x, g_pre_x);
    cudaGetSymbolAddress((void**)&pre_y, g_pre_y);
    cudaGetSymbolAddress((void**)&hx,    g_hx);
    cudaGetSymbolAddress((void**)&hy,    g_hy);
    cudaGetSymbolAddress((void**)&psx,   g_psx);
    cudaGetSymbolAddress((void**)&psy,   g_psy);

    cudaFuncSetAttribute(recur_depth,
                         cudaFuncAttributeMaxDynamicSharedMemorySize, RECUR_SMEM);

    reset_flags_kernel<<<1, 128>>>();

    for (int d = 0; d < 3; d++) {
        // ---- prepass: input projection + fused biases ----
        if (d == 0) {
            gemm256_bias<<<dim3(B * S / 64, H / 64), 256>>>(src, Wx_ih, bx_ih, bx_hh, psx);
            gemm256_bias<<<dim3(B * T / 64, H / 64), 256>>>(trg, Wy_ih, by_ih, by_hh, psy);
        } else {
            gemm256_bias<<<dim3(B * S * T / 64, H / 64), 256>>>(
                hx, Wx_ih + (size_t)d * H * H, bx_ih + d * H, bx_hh + d * H, pre_x);
            gemm256_bias<<<dim3(B * S * T / 64, H / 64), 256>>>(
                hy, Wy_ih + (size_t)d * H * H, by_ih + d * H, by_hh + d * H, pre_y);
        }

        const int OS = (d == 2) ? 2 * H : H;   // per-(i,j) row stride
        float* Ox = (d == 2) ? out     : hx;   // slot 0
        float* Oy = (d == 2) ? out + H : hy;   // slot 1

        RArgs AX, AY;
        AX.W = Wx_hh + (size_t)d * H * H;
        AX.out = Ox; AX.o_sstep = T * OS; AX.o_sb = S * T * OS; AX.o_sq = OS;
        if (d == 0) { AX.pre = psx;   AX.p_sstep = H;     AX.p_sb = S * H;     AX.p_sq = 0; }
        else        { AX.pre = pre_x; AX.p_sstep = T * H; AX.p_sb = S * T * H; AX.p_sq = H; }

        AY.W = Wy_hh + (size_t)d * H * H;
        AY.out = Oy; AY.o_sstep = OS; AY.o_sb = S * T * OS; AY.o_sq = T * OS;
        if (d == 0) { AY.pre = psy;   AY.p_sstep = H; AY.p_sb = T * H;     AY.p_sq = 0;     }
        else        { AY.pre = pre_y; AY.p_sstep = H; AY.p_sb = S * T * H; AY.p_sq = T * H; }

        recur_depth<<<dim3(4, 16, 2), 256, RECUR_SMEM>>>(AX, AY, d * 128);
    }
}

// round 7
// speedup vs baseline: 1.8734x; 1.8734x over previous
#include <cuda_runtime.h>
#include <math.h>
#include <stdint.h>

constexpr int H = 256;
constexpr int B = 4;
constexpr int S = 128;
constexpr int T = 128;

typedef unsigned long long ull;

// Scratch (device globals — no allocation allowed)
__device__ float g_pre_x[(size_t)B * S * T * H];
__device__ float g_pre_y[(size_t)B * S * T * H];
__device__ float g_hx  [(size_t)B * S * T * H];
__device__ float g_hy  [(size_t)B * S * T * H];
__device__ float g_psx [(size_t)B * S * H];
__device__ float g_psy [(size_t)B * T * H];

// ---------------- packed f32x2 helpers ----------------
__device__ __forceinline__ void ffma2(ull& d, ull a, ull b) {
    asm("fma.rn.f32x2 %0, %1, %2, %0;" : "+l"(d) : "l"(a), "l"(b));
}
__device__ __forceinline__ float hsum2(ull v) {
    float lo, hi;
    asm("mov.b64 {%0, %1}, %2;" : "=f"(lo), "=f"(hi) : "l"(v));
    return lo + hi;
}
__device__ __forceinline__ uint32_t smem_u32(const void* p) {
    uint32_t a;
    asm("{ .reg .u64 t; cvta.to.shared.u64 t, %1; cvt.u32.u64 %0, t; }" : "=r"(a) : "l"(p));
    return a;
}
__device__ __forceinline__ uint32_t mapa_u32(uint32_t addr, uint32_t rank) {
    uint32_t r;
    asm("mapa.shared::cluster.u32 %0, %1, %2;" : "=r"(r) : "r"(addr), "r"(rank));
    return r;
}
__device__ __forceinline__ void st_cluster_f32(uint32_t addr, float v) {
    asm volatile("st.shared::cluster.f32 [%0], %1;" :: "r"(addr), "f"(v) : "memory");
}
#define CLUSTER_SYNC() do { \
    asm volatile("barrier.cluster.arrive.aligned;" ::: "memory"); \
    asm volatile("barrier.cluster.wait.aligned;" ::: "memory"); \
} while (0)

// Accurate tanh regardless of --use_fast_math
__device__ __forceinline__ float my_tanh(float x) {
    float ax = fabsf(x);
    float e  = expf(-2.0f * ax);
    float t  = (1.0f - e) / (1.0f + e);
    return x < 0.0f ? -t : t;
}

// ---------------------------------------------------------------------------
// Prepass GEMM (k-split f32x2): C[m,n] = sum_k A[m,k]*W[n,k] + b1[n] + b2[n]
// N=K=256. BM=BN=64, BK=32, 256 thr, 4m x 4n per thread.
// Acc lanes hold {even-k, odd-k} partials; horizontal add at the end.
// No operand duplication: both A and W pairs are natural contiguous k-pairs.
// ---------------------------------------------------------------------------
__global__ void __launch_bounds__(256, 2) gemm256_bias(
    const float* __restrict__ A, const float* __restrict__ W,
    const float* __restrict__ b1, const float* __restrict__ b2,
    float* __restrict__ C)
{
    __shared__ float As[64][36];   // [m][k] row-major, +4 pad
    __shared__ float Bs[64][36];   // [n][k]

    const int m0  = blockIdx.x << 6;
    const int n0  = blockIdx.y << 6;
    const int tid = threadIdx.x;
    const int tx  = tid & 15;        // n lanes (cols tx + 16j)
    const int ty  = tid >> 4;        // m tile (4 rows)
    const int lr  = tid >> 2;        // 0..63 load row
    const int lk  = (tid & 3) << 2;  // 0,4,8,12

    const float* Ap = A + (size_t)(m0 + lr) * H + lk;
    const float* Wp = W + (size_t)(n0 + lr) * H + lk;

    float4 ra0 = *(const float4*)(Ap);
    float4 ra1 = *(const float4*)(Ap + 16);
    float4 rw0 = *(const float4*)(Wp);
    float4 rw1 = *(const float4*)(Wp + 16);

    ull acc[4][4] = {};

    for (int c = 0; c < 8; c++) {
        *(float4*)&As[lr][lk]      = ra0;
        *(float4*)&As[lr][lk + 16] = ra1;
        *(float4*)&Bs[lr][lk]      = rw0;
        *(float4*)&Bs[lr][lk + 16] = rw1;
        __syncthreads();

        if (c < 7) {
            int k = (c + 1) << 5;
            ra0 = *(const float4*)(Ap + k);
            ra1 = *(const float4*)(Ap + k + 16);
            rw0 = *(const float4*)(Wp + k);
            rw1 = *(const float4*)(Wp + k + 16);
        }

        #pragma unroll
        for (int kk = 0; kk < 32; kk += 4) {
            ulonglong2 Av[4], Wv[4];
            #pragma unroll
            for (int i = 0; i < 4; i++)
                Av[i] = *(const ulonglong2*)&As[(ty << 2) + i][kk];
            #pragma unroll
            for (int j = 0; j < 4; j++)
                Wv[j] = *(const ulonglong2*)&Bs[tx + (j << 4)][kk];
            #pragma unroll
            for (int i = 0; i < 4; i++)
                #pragma unroll
                for (int j = 0; j < 4; j++)
                    ffma2(acc[i][j], Av[i].x, Wv[j].x);
            #pragma unroll
            for (int i = 0; i < 4; i++)
                #pragma unroll
                for (int j = 0; j < 4; j++)
                    ffma2(acc[i][j], Av[i].y, Wv[j].y);
        }
        __syncthreads();
    }

    float bv[4];
    #pragma unroll
    for (int j = 0; j < 4; j++) {
        int n = n0 + tx + (j << 4);
        bv[j] = b1[n] + b2[n];
    }
    #pragma unroll
    for (int i = 0; i < 4; i++) {
        float* Cp = C + (size_t)(m0 + (ty << 2) + i) * H + n0 + tx;
        #pragma unroll
        for (int j = 0; j < 4; j++)
            Cp[j << 4] = hsum2(acc[i][j]) + bv[j];
    }
}

// ---------------------------------------------------------------------------
// Recurrence: diagonal chains, cluster-2, W resident in SMEM, state in SMEM.
// grid (2, 64), cluster (2,1,1). CTA rank r owns output cols [r*128, r*128+128).
// Cluster cl: path = cl>>5, grp = cl&31 -> b = grp>>3, chains dbase = (grp&7)*16.
// Each CTA: 16 chains x 128 cols per step; per-step state exchange via DSMEM.
// ---------------------------------------------------------------------------
struct RP {
    const float* W;                       // [256n][256k] row-major (this path+depth)
    const float* pre; long p_sb, p_sstep, p_sj;
    float*       out; long o_sb, o_sstep, o_sj;
    int diag;                             // 1 = x-path (j advances with step)
};

constexpr int WS_FLOATS = 128 * 260;          // 33280
constexpr int AS_FLOATS = 16 * 260;           // 4160 per buffer
constexpr int RECUR_SMEM = (WS_FLOATS + 2 * AS_FLOATS) * 4;   // 166400 B

__global__ void __launch_bounds__(256, 1) __cluster_dims__(2, 1, 1)
recur2(RP X, RP Y)
{
    extern __shared__ float sm[];
    float* Ws  = sm;                       // [128][260]
    float* As0 = sm + WS_FLOATS;           // [16][260]
    float* As1 = As0 + AS_FLOATS;

    const int rank  = blockIdx.x;          // cluster rank 0/1
    const int cl    = blockIdx.y;
    const int path  = cl >> 5;
    const RP  P     = path ? Y : X;
    const int grp   = cl & 31;
    const int b     = grp >> 3;
    const int dbase = (grp & 7) << 4;

    const int tid = threadIdx.x;
    const int tx  = tid & 31;              // col lane: cols ng + 32j
    const int ty  = tid >> 5;              // chain pair: cA=2ty, cB=2ty+1
    const int cA  = ty << 1, cB = cA + 1;
    const int dA  = dbase + cA, dB = dbase + cB;
    const int ng  = (rank << 7) + tx;      // global col base

    // ---- load W tile [128 rows][256 k] once per depth ----
    {
        const float* Wg = P.W + (size_t)(rank << 7) * H;
        #pragma unroll
        for (int idx = tid; idx < 128 * 64; idx += 256) {
            int row = idx >> 6, kq = (idx & 63) << 2;
            *(float4*)&Ws[row * 260 + kq] = *(const float4*)&Wg[row * H + kq];
        }
    }

    const uint32_t as0U  = smem_u32(As0);
    const uint32_t peerU = mapa_u32(as0U, rank ^ 1);

    const float* w0 = Ws + tx * 260;
    const float* w1 = Ws + (tx + 32) * 260;
    const float* w2 = Ws + (tx + 64) * 260;
    const float* w3 = Ws + (tx + 96) * 260;

    for (int st = 0; st < 128; st++) {
        const int jA = P.diag ? ((dA + st) & 127) : dA;
        const int jB = P.diag ? ((dB + st) & 127) : dB;

        // prefetch pre (needed only at epilogue; overlaps GEMM)
        const float* pA = P.pre + b * P.p_sb + st * P.p_sstep + jA * P.p_sj + ng;
        const float* pB = P.pre + b * P.p_sb + st * P.p_sstep + jB * P.p_sj + ng;
        float pvA[4], pvB[4];
        #pragma unroll
        for (int j = 0; j < 4; j++) { pvA[j] = pA[j << 5]; pvB[j] = pB[j << 5]; }

        ull acc[2][4] = {};
        if (st > 0) {
            const float* Ac = (st & 1) ? As1 : As0;   // buffer written at st-1
            const float* aA = Ac + cA * 260;
            const float* aB = Ac + cB * 260;
            #pragma unroll 8
            for (int k = 0; k < 256; k += 4) {
                ulonglong2 A0 = *(const ulonglong2*)(aA + k);
                ulonglong2 A1 = *(const ulonglong2*)(aB + k);
                ulonglong2 W0 = *(const ulonglong2*)(w0 + k);
                ulonglong2 W1 = *(const ulonglong2*)(w1 + k);
                ulonglong2 W2 = *(const ulonglong2*)(w2 + k);
                ulonglong2 W3 = *(const ulonglong2*)(w3 + k);
                ffma2(acc[0][0], A0.x, W0.x); ffma2(acc[0][1], A0.x, W1.x);
                ffma2(acc[0][2], A0.x, W2.x); ffma2(acc[0][3], A0.x, W3.x);
                ffma2(acc[1][0], A1.x, W0.x); ffma2(acc[1][1], A1.x, W1.x);
                ffma2(acc[1][2], A1.x, W2.x); ffma2(acc[1][3], A1.x, W3.x);
                ffma2(acc[0][0], A0.y, W0.y); ffma2(acc[0][1], A0.y, W1.y);
                ffma2(acc[0][2], A0.y, W2.y); ffma2(acc[0][3], A0.y, W3.y);
                ffma2(acc[1][0], A1.y, W0.y); ffma2(acc[1][1], A1.y, W1.y);
                ffma2(acc[1][2], A1.y, W2.y); ffma2(acc[1][3], A1.y, W3.y);
            }
        }

        float hA[4], hB[4];
        #pragma unroll
        for (int j = 0; j < 4; j++) {
            hA[j] = my_tanh(hsum2(acc[0][j]) + pvA[j]);
            hB[j] = my_tanh(hsum2(acc[1][j]) + pvB[j]);
        }

        // write result to global (no intra-kernel consumer)
        {
            float* oA = P.out + b * P.o_sb + st * P.o_sstep + jA * P.o_sj + ng;
            float* oB = P.out + b * P.o_sb + st * P.o_sstep + jB * P.o_sj + ng;
            #pragma unroll
            for (int j = 0; j < 4; j++) { oA[j << 5] = hA[j]; oB[j << 5] = hB[j]; }
        }

        // publish new state: own SMEM + peer SMEM (DSMEM), into buffer (st+1)&1
        if (st < 127) {
            float* An = (st & 1) ? As0 : As1;
            const uint32_t off = (uint32_t)((st & 1) ? 0 : AS_FLOATS * 4);
            const uint32_t pa  = peerU + off + (uint32_t)(cA * 260 + ng) * 4;
            const uint32_t pb2 = peerU + off + (uint32_t)(cB * 260 + ng) * 4;
            #pragma unroll
            for (int j = 0; j < 4; j++) {
                An[cA * 260 + ng + (j << 5)] = hA[j];
                An[cB * 260 + ng + (j << 5)] = hB[j];
                st_cluster_f32(pa  + (j << 7), hA[j]);
                st_cluster_f32(pb2 + (j << 7), hB[j]);
            }
        }
        CLUSTER_SYNC();   // orders state stores (incl. DSMEM) before next step
    }
}

// ---------------------------------------------------------------------------
// Host orchestration: 3 x (prepass GEMMs + 1 cluster recurrence) = 9 launches.
// ---------------------------------------------------------------------------
extern "C" void kernel_launch(void* const* d_in, const int* in_sizes, int n_in,
                              void* d_out, int out_size)
{
    const float* src   = (const float*)d_in[0];
    const float* trg   = (const float*)d_in[1];
    const float* Wx_ih = (const float*)d_in[2];
    const float* Wx_hh = (const float*)d_in[3];
    const float* bx_ih = (const float*)d_in[4];
    const float* bx_hh = (const float*)d_in[5];
    const float* Wy_ih = (const float*)d_in[6];
    const float* Wy_hh = (const float*)d_in[7];
    const float* by_ih = (const float*)d_in[8];
    const float* by_hh = (const float*)d_in[9];
    float* out = (float*)d_out;

    float *pre_x, *pre_y, *hx, *hy, *psx, *psy;
    cudaGetSymbolAddress((void**)&pre_x, g_pre_x);
    cudaGetSymbolAddress((void**)&pre_y, g_pre_y);
    cudaGetSymbolAddress((void**)&hx,    g_hx);
    cudaGetSymbolAddress((void**)&hy,    g_hy);
    cudaGetSymbolAddress((void**)&psx,   g_psx);
    cudaGetSymbolAddress((void**)&psy,   g_psy);

    cudaFuncSetAttribute(recur2,
                         cudaFuncAttributeMaxDynamicSharedMemorySize, RECUR_SMEM);

    for (int d = 0; d < 3; d++) {
        // ---- prepass: input projection + fused biases ----
        if (d == 0) {
            gemm256_bias<<<dim3(B * S / 64, H / 64), 256>>>(src, Wx_ih, bx_ih, bx_hh, psx);
            gemm256_bias<<<dim3(B * T / 64, H / 64), 256>>>(trg, Wy_ih, by_ih, by_hh, psy);
        } else {
            gemm256_bias<<<dim3(B * S * T / 64, H / 64), 256>>>(
                hx, Wx_ih + (size_t)d * H * H, bx_ih + d * H, bx_hh + d * H, pre_x);
            gemm256_bias<<<dim3(B * S * T / 64, H / 64), 256>>>(
                hy, Wy_ih + (size_t)d * H * H, by_ih + d * H, by_hh + d * H, pre_y);
        }

        const long OS = (d == 2) ? 2 * H : H;
        float* Ox = (d == 2) ? out     : hx;
        float* Oy = (d == 2) ? out + H : hy;

        RP X, Y;
        X.W = Wx_hh + (size_t)d * H * H;  X.diag = 1;
        X.out = Ox; X.o_sb = (long)S * T * OS; X.o_sstep = (long)T * OS; X.o_sj = OS;
        if (d == 0) { X.pre = psx;   X.p_sb = (long)S * H;     X.p_sstep = H;           X.p_sj = 0; }
        else        { X.pre = pre_x; X.p_sb = (long)S * T * H; X.p_sstep = (long)T * H; X.p_sj = H; }

        Y.W = Wy_hh + (size_t)d * H * H;  Y.diag = 0;
        Y.out = Oy; Y.o_sb = (long)S * T * OS; Y.o_sstep = OS; Y.o_sj = (long)T * OS;
        if (d == 0) { Y.pre = psy;   Y.p_sb = (long)T * H;     Y.p_sstep = H; Y.p_sj = 0; }
        else        { Y.pre = pre_y; Y.p_sb = (long)S * T * H; Y.p_sstep = H; Y.p_sj = (long)T * H; }

        recur2<<<dim3(2, 64), 256, RECUR_SMEM>>>(X, Y);
    }
}

// round 8
// speedup vs baseline: 2.2515x; 1.2018x over previous
#include <cuda_runtime.h>
#include <math.h>
#include <stdint.h>

constexpr int H = 256;
constexpr int B = 4;
constexpr int S = 128;
constexpr int T = 128;

typedef unsigned long long ull;

// Scratch (device globals — no allocation allowed)
__device__ float g_pre_x[(size_t)B * S * T * H];
__device__ float g_pre_y[(size_t)B * S * T * H];
__device__ float g_hx  [(size_t)B * S * T * H];
__device__ float g_hy  [(size_t)B * S * T * H];
__device__ float g_psx [(size_t)B * S * H];
__device__ float g_psy [(size_t)B * T * H];

// ---------------- packed f32x2 helpers ----------------
__device__ __forceinline__ void ffma2(ull& d, ull a, ull b) {
    asm("fma.rn.f32x2 %0, %1, %2, %0;" : "+l"(d) : "l"(a), "l"(b));
}
__device__ __forceinline__ float hsum2(ull v) {
    float lo, hi;
    asm("mov.b64 {%0, %1}, %2;" : "=f"(lo), "=f"(hi) : "l"(v));
    return lo + hi;
}
__device__ __forceinline__ ull packf2(float a, float b) {
    ull r; asm("mov.b64 %0, {%1, %2};" : "=l"(r) : "f"(a), "f"(b)); return r;
}
__device__ __forceinline__ uint32_t smem_u32(const void* p) {
    uint32_t a;
    asm("{ .reg .u64 t; cvta.to.shared.u64 t, %1; cvt.u32.u64 %0, t; }" : "=r"(a) : "l"(p));
    return a;
}
__device__ __forceinline__ uint32_t mapa_u32(uint32_t addr, uint32_t rank) {
    uint32_t r;
    asm("mapa.shared::cluster.u32 %0, %1, %2;" : "=r"(r) : "r"(addr), "r"(rank));
    return r;
}
__device__ __forceinline__ void st_cluster_b64(uint32_t addr, ull v) {
    asm volatile("st.shared::cluster.b64 [%0], %1;" :: "r"(addr), "l"(v) : "memory");
}
#define CLUSTER_SYNC() do { \
    asm volatile("barrier.cluster.arrive.aligned;" ::: "memory"); \
    asm volatile("barrier.cluster.wait.aligned;" ::: "memory"); \
} while (0)

// Accurate tanh regardless of --use_fast_math
__device__ __forceinline__ float my_tanh(float x) {
    float ax = fabsf(x);
    float e  = expf(-2.0f * ax);
    float t  = (1.0f - e) / (1.0f + e);
    return x < 0.0f ? -t : t;
}

// ---------------------------------------------------------------------------
// Prepass GEMM (k-split f32x2): C[m,n] = sum_k A[m,k]*W[n,k] + b1[n] + b2[n]
// N=K=256. BM=128, BN=64, BK=32, 256 thr, 8m x 4n per thread.
// Row interleave (ty + 16i) keeps A smem loads bank-conflict-free.
// ---------------------------------------------------------------------------
__global__ void __launch_bounds__(256, 1) gemm256_bias(
    const float* __restrict__ A, const float* __restrict__ W,
    const float* __restrict__ b1, const float* __restrict__ b2,
    float* __restrict__ C)
{
    __shared__ float As[128 * 36];   // [m][k], +4 pad
    __shared__ float Bs[64 * 36];    // [n][k]

    const int m0  = blockIdx.x << 7;
    const int n0  = blockIdx.y << 6;
    const int tid = threadIdx.x;
    const int tx  = tid & 15;        // n lanes (cols tx + 16j)
    const int ty  = tid >> 4;        // m lanes (rows ty + 16i)
    const int lr0 = tid >> 3;        // 0..31 base load row
    const int lk  = (tid & 7) << 2;  // 0,4,...,28

    const float* Ap = A + (size_t)(m0 + lr0) * H + lk;
    const float* Wp = W + (size_t)(n0 + lr0) * H + lk;

    float4 pa[4], pb[2];
    #pragma unroll
    for (int s = 0; s < 4; s++) pa[s] = *(const float4*)(Ap + (size_t)(s << 5) * H);
    #pragma unroll
    for (int s = 0; s < 2; s++) pb[s] = *(const float4*)(Wp + (size_t)(s << 5) * H);

    ull acc[8][4] = {};

    for (int c = 0; c < 8; c++) {
        #pragma unroll
        for (int s = 0; s < 4; s++)
            *(float4*)&As[(lr0 + (s << 5)) * 36 + lk] = pa[s];
        #pragma unroll
        for (int s = 0; s < 2; s++)
            *(float4*)&Bs[(lr0 + (s << 5)) * 36 + lk] = pb[s];
        __syncthreads();

        if (c < 7) {
            int k = (c + 1) << 5;
            #pragma unroll
            for (int s = 0; s < 4; s++) pa[s] = *(const float4*)(Ap + (size_t)(s << 5) * H + k);
            #pragma unroll
            for (int s = 0; s < 2; s++) pb[s] = *(const float4*)(Wp + (size_t)(s << 5) * H + k);
        }

        #pragma unroll
        for (int kk = 0; kk < 32; kk += 4) {
            ulonglong2 Av[8], Wv[4];
            #pragma unroll
            for (int i = 0; i < 8; i++)
                Av[i] = *(const ulonglong2*)&As[(ty + (i << 4)) * 36 + kk];
            #pragma unroll
            for (int j = 0; j < 4; j++)
                Wv[j] = *(const ulonglong2*)&Bs[(tx + (j << 4)) * 36 + kk];
            #pragma unroll
            for (int i = 0; i < 8; i++)
                #pragma unroll
                for (int j = 0; j < 4; j++)
                    ffma2(acc[i][j], Av[i].x, Wv[j].x);
            #pragma unroll
            for (int i = 0; i < 8; i++)
                #pragma unroll
                for (int j = 0; j < 4; j++)
                    ffma2(acc[i][j], Av[i].y, Wv[j].y);
        }
        __syncthreads();
    }

    float bv[4];
    #pragma unroll
    for (int j = 0; j < 4; j++) {
        int n = n0 + tx + (j << 4);
        bv[j] = b1[n] + b2[n];
    }
    #pragma unroll
    for (int i = 0; i < 8; i++) {
        float* Cp = C + (size_t)(m0 + ty + (i << 4)) * H + n0 + tx;
        #pragma unroll
        for (int j = 0; j < 4; j++)
            Cp[j << 4] = hsum2(acc[i][j]) + bv[j];
    }
}

// ---------------------------------------------------------------------------
// Recurrence: diagonal chains, cluster-2, W resident in SMEM (kpair-interleaved),
// state double-buffered in SMEM, DSMEM exchange, one cluster.sync per step.
// grid (2, 64), cluster (2,1,1), 128 threads.
// Lane = 4 chains x 4 cols; warp = all 16 chains x 32 cols -> W loads are
// contiguous 128B wavefronts broadcast across chain groups.
// ---------------------------------------------------------------------------
struct RP {
    const float* W;                       // [256n][256k] row-major (this path+depth)
    const float* pre; long p_sb, p_sstep, p_sj;
    float*       out; long o_sb, o_sstep, o_sj;
    int diag;                             // 1 = x-path (j advances with step)
};

constexpr int W2_FLOATS = 128 * 260;          // [kpair][2*col(128)+pad]
constexpr int AS_FLOATS = 16 * 260;           // [chain][k(256)+pad]
constexpr int RECUR_SMEM = (W2_FLOATS + 2 * AS_FLOATS) * 4;   // 166400 B

__global__ void __launch_bounds__(128, 1) __cluster_dims__(2, 1, 1)
recur2(RP X, RP Y)
{
    extern __shared__ float sm[];
    float* W2  = sm;                       // [128 kpairs][260]
    float* As0 = sm + W2_FLOATS;           // [16][260]
    float* As1 = As0 + AS_FLOATS;

    const int rank  = blockIdx.x;          // cluster rank 0/1
    const int clid  = blockIdx.y;
    const int path  = clid >> 5;
    const RP  P     = path ? Y : X;
    const int grp   = clid & 31;
    const int b     = grp >> 3;
    const int dbase = (grp & 7) << 4;

    const int tid  = threadIdx.x;
    const int w    = tid >> 5;             // warp 0..3 (32 cols each)
    const int lane = tid & 31;
    const int cg   = lane >> 3;            // chain group 0..3
    const int cls  = lane & 7;             // col lane 0..7
    const int c0L  = (w << 5) + (cls << 1);   // local cols c0L, c0L+1, c0L+16, c0L+17
    const int gc0  = (rank << 7) + c0L;

    int lc[4], dch[4];
    #pragma unroll
    for (int i = 0; i < 4; i++) { lc[i] = cg + (i << 2); dch[i] = dbase + lc[i]; }

    // ---- fill W2: W2[p][2c..2c+1] = {W[c][2p], W[c][2p+1]}, c = local col ----
    {
        const float* Wg = P.W + (size_t)(rank << 7) * H;
        for (int idx = tid; idx < 128 * 64; idx += 128) {
            int c = idx >> 6, kq = (idx & 63) << 2;
            float4 v = *(const float4*)&Wg[(size_t)c * H + kq];
            int p0 = kq >> 1;
            *(float2*)&W2[p0 * 260 + (c << 1)]       = make_float2(v.x, v.y);
            *(float2*)&W2[(p0 + 1) * 260 + (c << 1)] = make_float2(v.z, v.w);
        }
    }

    const uint32_t as0U  = smem_u32(As0);
    const uint32_t peerU = mapa_u32(as0U, rank ^ 1);

    const float* wBase = W2 + (c0L << 1);

    for (int st = 0; st < 128; st++) {
        int jc[4];
        #pragma unroll
        for (int i = 0; i < 4; i++)
            jc[i] = P.diag ? ((dch[i] + st) & 127) : dch[i];

        // prefetch pre (overlaps GEMM / sync)
        float2 pre0[4], pre1[4];
        #pragma unroll
        for (int i = 0; i < 4; i++) {
            const float* pp = P.pre + b * P.p_sb + st * P.p_sstep + jc[i] * P.p_sj + gc0;
            pre0[i] = *(const float2*)(pp);
            pre1[i] = *(const float2*)(pp + 16);
        }

        ull acc[4][4] = {};
        if (st > 0) {
            const float* Ac = (st & 1) ? As1 : As0;
            const float* a0 = Ac + lc[0] * 260;
            const float* a1 = Ac + lc[1] * 260;
            const float* a2 = Ac + lc[2] * 260;
            const float* a3 = Ac + lc[3] * 260;
            #pragma unroll 8
            for (int k = 0; k < 256; k += 4) {
                ulonglong2 A0 = *(const ulonglong2*)(a0 + k);
                ulonglong2 A1 = *(const ulonglong2*)(a1 + k);
                ulonglong2 A2 = *(const ulonglong2*)(a2 + k);
                ulonglong2 A3 = *(const ulonglong2*)(a3 + k);
                const float* wp = wBase + (k >> 1) * 260;
                ulonglong2 L0 = *(const ulonglong2*)(wp);          // kpair p, cols c0,c1
                ulonglong2 L1 = *(const ulonglong2*)(wp + 32);     // kpair p, cols c2,c3
                ulonglong2 L2 = *(const ulonglong2*)(wp + 260);    // kpair p+1, c0,c1
                ulonglong2 L3 = *(const ulonglong2*)(wp + 292);    // kpair p+1, c2,c3
                ffma2(acc[0][0], A0.x, L0.x); ffma2(acc[0][1], A0.x, L0.y);
                ffma2(acc[0][2], A0.x, L1.x); ffma2(acc[0][3], A0.x, L1.y);
                ffma2(acc[1][0], A1.x, L0.x); ffma2(acc[1][1], A1.x, L0.y);
                ffma2(acc[1][2], A1.x, L1.x); ffma2(acc[1][3], A1.x, L1.y);
                ffma2(acc[2][0], A2.x, L0.x); ffma2(acc[2][1], A2.x, L0.y);
                ffma2(acc[2][2], A2.x, L1.x); ffma2(acc[2][3], A2.x, L1.y);
                ffma2(acc[3][0], A3.x, L0.x); ffma2(acc[3][1], A3.x, L0.y);
                ffma2(acc[3][2], A3.x, L1.x); ffma2(acc[3][3], A3.x, L1.y);
                ffma2(acc[0][0], A0.y, L2.x); ffma2(acc[0][1], A0.y, L2.y);
                ffma2(acc[0][2], A0.y, L3.x); ffma2(acc[0][3], A0.y, L3.y);
                ffma2(acc[1][0], A1.y, L2.x); ffma2(acc[1][1], A1.y, L2.y);
                ffma2(acc[1][2], A1.y, L3.x); ffma2(acc[1][3], A1.y, L3.y);
                ffma2(acc[2][0], A2.y, L2.x); ffma2(acc[2][1], A2.y, L2.y);
                ffma2(acc[2][2], A2.y, L3.x); ffma2(acc[2][3], A2.y, L3.y);
                ffma2(acc[3][0], A3.y, L2.x); ffma2(acc[3][1], A3.y, L2.y);
                ffma2(acc[3][2], A3.y, L3.x); ffma2(acc[3][3], A3.y, L3.y);
            }
        }

        float h[4][4];
        #pragma unroll
        for (int i = 0; i < 4; i++) {
            h[i][0] = my_tanh(hsum2(acc[i][0]) + pre0[i].x);
            h[i][1] = my_tanh(hsum2(acc[i][1]) + pre0[i].y);
            h[i][2] = my_tanh(hsum2(acc[i][2]) + pre1[i].x);
            h[i][3] = my_tanh(hsum2(acc[i][3]) + pre1[i].y);
        }

        // global output
        #pragma unroll
        for (int i = 0; i < 4; i++) {
            float* op = P.out + b * P.o_sb + st * P.o_sstep + jc[i] * P.o_sj + gc0;
            *(float2*)(op)      = make_float2(h[i][0], h[i][1]);
            *(float2*)(op + 16) = make_float2(h[i][2], h[i][3]);
        }

        // publish state for step st+1: own SMEM + peer SMEM (DSMEM)
        if (st < 127) {
            float* An = (st & 1) ? As0 : As1;
            const uint32_t bufOff = (uint32_t)(((st & 1) ? 0 : AS_FLOATS) * 4);
            #pragma unroll
            for (int i = 0; i < 4; i++) {
                const int o0 = lc[i] * 260 + gc0;
                *(float2*)&An[o0]      = make_float2(h[i][0], h[i][1]);
                *(float2*)&An[o0 + 16] = make_float2(h[i][2], h[i][3]);
                st_cluster_b64(peerU + bufOff + (uint32_t)o0 * 4,        packf2(h[i][0], h[i][1]));
                st_cluster_b64(peerU + bufOff + (uint32_t)(o0 + 16) * 4, packf2(h[i][2], h[i][3]));
            }
        }
        CLUSTER_SYNC();   // orders state stores (incl. DSMEM) before next step
    }
}

// ---------------------------------------------------------------------------
// Host orchestration: 3 x (prepass GEMMs + 1 cluster recurrence) = 9 launches.
// ---------------------------------------------------------------------------
extern "C" void kernel_launch(void* const* d_in, const int* in_sizes, int n_in,
                              void* d_out, int out_size)
{
    const float* src   = (const float*)d_in[0];
    const float* trg   = (const float*)d_in[1];
    const float* Wx_ih = (const float*)d_in[2];
    const float* Wx_hh = (const float*)d_in[3];
    const float* bx_ih = (const float*)d_in[4];
    const float* bx_hh = (const float*)d_in[5];
    const float* Wy_ih = (const float*)d_in[6];
    const float* Wy_hh = (const float*)d_in[7];
    const float* by_ih = (const float*)d_in[8];
    const float* by_hh = (const float*)d_in[9];
    float* out = (float*)d_out;

    float *pre_x, *pre_y, *hx, *hy, *psx, *psy;
    cudaGetSymbolAddress((void**)&pre_x, g_pre_x);
    cudaGetSymbolAddress((void**)&pre_y, g_pre_y);
    cudaGetSymbolAddress((void**)&hx,    g_hx);
    cudaGetSymbolAddress((void**)&hy,    g_hy);
    cudaGetSymbolAddress((void**)&psx,   g_psx);
    cudaGetSymbolAddress((void**)&psy,   g_psy);

    cudaFuncSetAttribute(recur2,
                         cudaFuncAttributeMaxDynamicSharedMemorySize, RECUR_SMEM);

    for (int d = 0; d < 3; d++) {
        // ---- prepass: input projection + fused biases ----
        if (d == 0) {
            gemm256_bias<<<dim3(B * S / 128, H / 64), 256>>>(src, Wx_ih, bx_ih, bx_hh, psx);
            gemm256_bias<<<dim3(B * T / 128, H / 64), 256>>>(trg, Wy_ih, by_ih, by_hh, psy);
        } else {
            gemm256_bias<<<dim3(B * S * T / 128, H / 64), 256>>>(
                hx, Wx_ih + (size_t)d * H * H, bx_ih + d * H, bx_hh + d * H, pre_x);
            gemm256_bias<<<dim3(B * S * T / 128, H / 64), 256>>>(
                hy, Wy_ih + (size_t)d * H * H, by_ih + d * H, by_hh + d * H, pre_y);
        }

        const long OS = (d == 2) ? 2 * H : H;
        float* Ox = (d == 2) ? out     : hx;
        float* Oy = (d == 2) ? out + H : hy;

        RP X, Y;
        X.W = Wx_hh + (size_t)d * H * H;  X.diag = 1;
        X.out = Ox; X.o_sb = (long)S * T * OS; X.o_sstep = (long)T * OS; X.o_sj = OS;
        if (d == 0) { X.pre = psx;   X.p_sb = (long)S * H;     X.p_sstep = H;           X.p_sj = 0; }
        else        { X.pre = pre_x; X.p_sb = (long)S * T * H; X.p_sstep = (long)T * H; X.p_sj = H; }

        Y.W = Wy_hh + (size_t)d * H * H;  Y.diag = 0;
        Y.out = Oy; Y.o_sb = (long)S * T * OS; Y.o_sstep = OS; Y.o_sj = (long)T * OS;
        if (d == 0) { Y.pre = psy;   Y.p_sb = (long)T * H;     Y.p_sstep = H; Y.p_sj = 0; }
        else        { Y.pre = pre_y; Y.p_sb = (long)S * T * H; Y.p_sstep = H; Y.p_sj = (long)T * H; }

        recur2<<<dim3(2, 64), 128, RECUR_SMEM>>>(X, Y);
    }
}